// round 7
// baseline (speedup 1.0000x reference)
#include <cuda_runtime.h>
#include <cstdint>
#include <math.h>

#define B_SLIDES 64
#define N_CELLS  20000
#define NI       64
#define H1       16
#define H2       8
#define N_OUT    2

#define TPB      64                  // 2 warps
#define CSTAGE   128                 // cells staged per iteration (2 per thread)
#define ROW      68                  // padded floats per SMEM row (16B-aligned, conflict-free)
#define CHUNKS   13
#define CELLS_PER_CHUNK ((N_CELLS + CHUNKS - 1) / CHUNKS)   // 1539
#define TOTAL_BLOCKS (CHUNKS * B_SLIDES)                    // 832 (<= 6*148=888, one wave)

#define XS_FLOATS (CSTAGE * ROW)     // 8704 floats = 34816 B
#define SMEM_BYTES (XS_FLOATS * 4 + 64 * 8 + 4 * 8 + 8 * 4 + 9 * 2 * 4 + 64)

typedef unsigned long long ull;

// ---- W1 (+b1) in constant memory: loads go to the constant port, NOT L1 ----
__constant__ ull   cW1p[NI * H1 / 2];   // W1[64][16] raw -> [64][8] fp32-pairs (4KB)
__constant__ float cb1[H1];

__device__ float        g_partials[B_SLIDES * CHUNKS * 9];
__device__ unsigned int g_count = 0;

__device__ __forceinline__ ull pack2(float lo, float hi) {
    ull r; asm("mov.b64 %0, {%1, %2};" : "=l"(r) : "f"(lo), "f"(hi)); return r;
}
__device__ __forceinline__ void unpack2(ull v, float& lo, float& hi) {
    asm("mov.b64 {%0, %1}, %2;" : "=f"(lo), "=f"(hi) : "l"(v));
}
// Packed fp32x2 FMA (sm_100+): two fp32 FMAs per instruction.
__device__ __forceinline__ ull fma2(ull a, ull b, ull c) {
    ull d; asm("fma.rn.f32x2 %0, %1, %2, %3;" : "=l"(d) : "l"(a), "l"(b), "l"(c)); return d;
}
__device__ __forceinline__ float ldcg(const float* p) {
    float v; asm("ld.global.cg.f32 %0, [%1];" : "=f"(v) : "l"(p)); return v;
}

// Per-cell tail: relu(h1) -> layer2 -> relu -> gate -> gated accumulate.
__device__ __forceinline__ void cell_tail(const ull* acc, bool valid,
                                          const ull* __restrict__ w2q,
                                          const float* __restrict__ b2s,
                                          const ull* __restrict__ wwp,
                                          float bwv,
                                          float& sw, ull* swh)
{
    float h1[H1];
    #pragma unroll
    for (int jp = 0; jp < 8; ++jp) {
        float lo, hi; unpack2(acc[jp], lo, hi);
        h1[2 * jp]     = fmaxf(lo, 0.f);
        h1[2 * jp + 1] = fmaxf(hi, 0.f);
    }

    ull acc2[4];
    #pragma unroll
    for (int kp = 0; kp < 4; ++kp) acc2[kp] = pack2(b2s[2 * kp], b2s[2 * kp + 1]);
    const ulonglong2* w2p = (const ulonglong2*)w2q;   // [16][2] of ull2 (SMEM bcast)
    #pragma unroll
    for (int i = 0; i < H1; ++i) {
        ull hx = pack2(h1[i], h1[i]);
        ulonglong2 wa = w2p[i * 2 + 0];
        ulonglong2 wb = w2p[i * 2 + 1];
        acc2[0] = fma2(hx, wa.x, acc2[0]);
        acc2[1] = fma2(hx, wa.y, acc2[1]);
        acc2[2] = fma2(hx, wb.x, acc2[2]);
        acc2[3] = fma2(hx, wb.y, acc2[3]);
    }

    float h2[H2];
    #pragma unroll
    for (int kp = 0; kp < 4; ++kp) {
        float lo, hi; unpack2(acc2[kp], lo, hi);
        h2[2 * kp]     = fmaxf(lo, 0.f);
        h2[2 * kp + 1] = fmaxf(hi, 0.f);
    }

    ull g = pack2(bwv, 0.f);
    #pragma unroll
    for (int kp = 0; kp < 4; ++kp)
        g = fma2(pack2(h2[2 * kp], h2[2 * kp + 1]), wwp[kp], g);
    float glo, ghi; unpack2(g, glo, ghi);
    float wgt = 1.f / (1.f + __expf(-(glo + ghi)));
    if (!valid) wgt = 0.f;

    sw += wgt;
    ull wp = pack2(wgt, wgt);
    #pragma unroll
    for (int kp = 0; kp < 4; ++kp)
        swh[kp] = fma2(wp, pack2(h2[2 * kp], h2[2 * kp + 1]), swh[kp]);
}

__global__ __launch_bounds__(TPB, 6) void mlp_pool_kernel(
    const float* __restrict__ X,
    const float* __restrict__ W2, const float* __restrict__ b2,
    const float* __restrict__ Ww, const float* __restrict__ bw,
    const float* __restrict__ W4, const float* __restrict__ b4,
    float* __restrict__ out)
{
    extern __shared__ float smemf[];
    float* xs  = smemf;                                   // [CSTAGE][ROW]
    ull*   w2q = (ull*)(xs + XS_FLOATS);                  // 64 ull (W2 raw pairs)
    ull*   wwp = w2q + 64;                                // 4 ull
    float* b2s = (float*)(wwp + 4);                       // 8
    float* red = b2s + 8;                                 // 9 * 2
    __shared__ unsigned int s_last;

    const int tid   = threadIdx.x;
    const int b     = blockIdx.y;
    const int chunk = blockIdx.x;

    // ---- small weights -> SMEM ----
    if (tid < 64) w2q[tid] = ((const ull*)W2)[tid];
    if (tid < 4)  wwp[tid] = ((const ull*)Ww)[tid];
    if (tid < 8)  b2s[tid] = b2[tid];
    const float bwv = __ldg(bw);

    const int start = chunk * CELLS_PER_CHUNK;
    const int end   = min(start + CELLS_PER_CHUNK, N_CELLS);

    const float4* __restrict__ Xg = (const float4*)(X + (size_t)b * N_CELLS * NI);

    float sw = 0.f;
    ull swh[4];
    #pragma unroll
    for (int k = 0; k < 4; ++k) swh[k] = pack2(0.f, 0.f);

    for (int base = start; base < end; base += CSTAGE) {
        __syncthreads();                 // covers weight init + buffer reuse
        const int nv = min(end - base, CSTAGE);

        // ---- coalesced stage: 128 cells x 64 floats -> padded SMEM ----
        #pragma unroll 8
        for (int k = 0; k < 32; ++k) {
            int f = tid + k * TPB;        // 0..2047
            int c = f >> 4;               // cell 0..127
            int o = f & 15;               // float4 slot
            float4 v = make_float4(0.f, 0.f, 0.f, 0.f);
            if (c < nv) v = Xg[(size_t)(base + c) * (NI / 4) + o];
            *(float4*)&xs[c * ROW + o * 4] = v;
        }
        __syncthreads();

        // ---- layer 1 for 2 cells/thread; W1 from constant port ----
        ull accA[8], accB[8];
        #pragma unroll
        for (int jp = 0; jp < 8; ++jp) {
            ull bj = pack2(cb1[2 * jp], cb1[2 * jp + 1]);
            accA[jp] = bj; accB[jp] = bj;
        }

        const float4* xA = (const float4*)&xs[tid * ROW];
        const float4* xB = (const float4*)&xs[(tid + TPB) * ROW];

        #pragma unroll 4
        for (int i4 = 0; i4 < 16; ++i4) {
            float4 va = xA[i4];
            float4 vb = xB[i4];
            #pragma unroll
            for (int s = 0; s < 4; ++s) {
                float xa = (s == 0) ? va.x : (s == 1) ? va.y : (s == 2) ? va.z : va.w;
                float xb = (s == 0) ? vb.x : (s == 1) ? vb.y : (s == 2) ? vb.z : vb.w;
                ull xa2 = pack2(xa, xa);
                ull xb2 = pack2(xb, xb);
                const ulonglong2* wr = (const ulonglong2*)&cW1p[(i4 * 4 + s) * 8];
                #pragma unroll
                for (int q = 0; q < 4; ++q) {
                    ulonglong2 w = wr[q];                 // LDC/LDCU.128 (const port)
                    accA[2 * q + 0] = fma2(xa2, w.x, accA[2 * q + 0]);
                    accA[2 * q + 1] = fma2(xa2, w.y, accA[2 * q + 1]);
                    accB[2 * q + 0] = fma2(xb2, w.x, accB[2 * q + 0]);
                    accB[2 * q + 1] = fma2(xb2, w.y, accB[2 * q + 1]);
                }
            }
        }

        cell_tail(accA, tid < nv,       w2q, b2s, wwp, bwv, sw, swh);
        cell_tail(accB, tid + TPB < nv, w2q, b2s, wwp, bwv, sw, swh);
    }

    // ---- deterministic block reduction of 9 values (2 warps) ----
    float vals[9];
    vals[0] = sw;
    #pragma unroll
    for (int kp = 0; kp < 4; ++kp) {
        float lo, hi; unpack2(swh[kp], lo, hi);
        vals[1 + 2 * kp] = lo; vals[2 + 2 * kp] = hi;
    }
    #pragma unroll
    for (int off = 16; off > 0; off >>= 1) {
        #pragma unroll
        for (int k = 0; k < 9; ++k)
            vals[k] += __shfl_down_sync(0xffffffffu, vals[k], off);
    }
    const int lane = tid & 31, warp = tid >> 5;
    if (lane == 0) {
        #pragma unroll
        for (int k = 0; k < 9; ++k) red[k * 2 + warp] = vals[k];
    }
    __syncthreads();
    if (tid < 9)
        g_partials[((size_t)b * CHUNKS + chunk) * 9 + tid] = red[tid * 2] + red[tid * 2 + 1];

    // ---- last-block finalize (fused head; graph-replay-safe counter) ----
    __threadfence();
    __syncthreads();
    if (tid == 0) {
        unsigned int d = atomicAdd(&g_count, 1u);
        s_last = (d == TOTAL_BLOCKS - 1) ? 1u : 0u;
    }
    __syncthreads();

    if (s_last) {
        float* fs = xs;                  // reuse staging buffer: [64][9]
        for (int p = tid; p < B_SLIDES * 9; p += TPB) {
            int bb = p / 9, k = p % 9;
            float s = 0.f;
            #pragma unroll
            for (int c = 0; c < CHUNKS; ++c)
                s += ldcg(&g_partials[((size_t)bb * CHUNKS + c) * 9 + k]);
            fs[bb * 9 + k] = s;
        }
        __syncthreads();
        if (tid < B_SLIDES) {
            float inv = 1.f / fs[tid * 9];
            #pragma unroll
            for (int o = 0; o < N_OUT; ++o) {
                float r = b4[o];
                #pragma unroll
                for (int k = 0; k < H2; ++k)
                    r += (fs[tid * 9 + 1 + k] * inv) * W4[k * N_OUT + o];
                out[tid * N_OUT + o] = r;
            }
        }
        if (tid == 0) atomicExch(&g_count, 0u);   // reset for next graph replay
    }
}

extern "C" void kernel_launch(void* const* d_in, const int* in_sizes, int n_in,
                              void* d_out, int out_size)
{
    (void)in_sizes; (void)n_in; (void)out_size;

    // W1 + b1 into constant memory (raw D2D copies, graph-capturable).
    cudaMemcpyToSymbolAsync(cW1p, d_in[1], NI * H1 * sizeof(float), 0,
                            cudaMemcpyDeviceToDevice, 0);
    cudaMemcpyToSymbolAsync(cb1,  d_in[2], H1 * sizeof(float), 0,
                            cudaMemcpyDeviceToDevice, 0);

    cudaFuncSetAttribute(mlp_pool_kernel,
                         cudaFuncAttributeMaxDynamicSharedMemorySize, SMEM_BYTES);
    dim3 grid(CHUNKS, B_SLIDES);
    mlp_pool_kernel<<<grid, TPB, SMEM_BYTES>>>(
        (const float*)d_in[0],
        (const float*)d_in[3], (const float*)d_in[4],
        (const float*)d_in[5], (const float*)d_in[6],
        (const float*)d_in[7], (const float*)d_in[8],
        (float*)d_out);
}

// round 9
// speedup vs baseline: 1.4612x; 1.4612x over previous
#include <cuda_runtime.h>
#include <cstdint>
#include <math.h>

#define B_SLIDES 64
#define N_CELLS  20000
#define NI       64
#define H1       16
#define H2       8
#define N_OUT    2

#define TPB      128                 // 4 warps
#define CSTAGE   128                 // cells staged per iteration (1 per thread)
#define CHUNKS   13
#define CELLS_PER_CHUNK ((N_CELLS + CHUNKS - 1) / CHUNKS)   // 1539
#define TOTAL_BLOCKS (CHUNKS * B_SLIDES)                    // 832 (<= 6*148=888, one wave)

// Staging: 128 rows x 256 bytes, XOR-swizzled in 16B units (conflict-free R/W)
#define XS_BYTES (CSTAGE * 256)      // 32768
// + W1 high half (32 rows x 16 f = 2KB) + W2 (512B) + gate/bias/red (~200B)
#define SMEM_BYTES (XS_BYTES + 2048 + 512 + 32 + 32 + 96 + 64)

typedef unsigned long long ull;

// ---- W1 low half (+b1) in constant memory (constant port) ----
__constant__ ull   cW1p[32 * H1 / 2];   // W1 rows 0..31 as fp32-pairs (2KB)
__constant__ float cb1[H1];

__device__ float        g_partials[B_SLIDES * CHUNKS * 9];
__device__ unsigned int g_count = 0;

__device__ __forceinline__ ull pack2(float lo, float hi) {
    ull r; asm("mov.b64 %0, {%1, %2};" : "=l"(r) : "f"(lo), "f"(hi)); return r;
}
__device__ __forceinline__ void unpack2(ull v, float& lo, float& hi) {
    asm("mov.b64 {%0, %1}, %2;" : "=f"(lo), "=f"(hi) : "l"(v));
}
// Packed fp32x2 FMA (sm_100+): two fp32 FMAs per instruction.
__device__ __forceinline__ ull fma2(ull a, ull b, ull c) {
    ull d; asm("fma.rn.f32x2 %0, %1, %2, %3;" : "=l"(d) : "l"(a), "l"(b), "l"(c)); return d;
}
__device__ __forceinline__ float ldcg(const float* p) {
    float v; asm("ld.global.cg.f32 %0, [%1];" : "=f"(v) : "l"(p)); return v;
}

// row-XOR swizzle: 16B column col within 256B row r -> col ^ (r & 7)
__device__ __forceinline__ uint32_t xs_off(int row, int col16) {
    return ((uint32_t)row << 8) + (((uint32_t)(col16 ^ (row & 7))) << 4);
}

__global__ __launch_bounds__(TPB, 6) void mlp_pool_kernel(
    const float* __restrict__ X,
    const float* __restrict__ W1, const float* __restrict__ b1_unused,
    const float* __restrict__ W2, const float* __restrict__ b2,
    const float* __restrict__ Ww, const float* __restrict__ bw,
    const float* __restrict__ W4, const float* __restrict__ b4,
    float* __restrict__ out)
{
    extern __shared__ char smem[];
    char* xs   = smem;                                    // 32KB swizzled staging
    ull*  w1s  = (ull*)(smem + XS_BYTES);                 // 256 ull: W1 rows 32..63
    ull*  w2q  = w1s + 256;                               // 64 ull (W2 raw pairs)
    ull*  wwp  = w2q + 64;                                // 4 ull
    float* b2s = (float*)(wwp + 4);                       // 8
    float* red = b2s + 8;                                 // 9 * 4
    __shared__ unsigned int s_last;

    const int tid   = threadIdx.x;
    const int b     = blockIdx.y;
    const int chunk = blockIdx.x;

    // ---- weights -> SMEM: W1 high half + small tail weights ----
    {
        const ull* W1q = (const ull*)W1;                  // [64][8] pairs
        #pragma unroll
        for (int k = 0; k < 2; ++k)
            w1s[tid + k * TPB] = W1q[256 + tid + k * TPB]; // rows 32..63
    }
    if (tid < 64) w2q[tid] = ((const ull*)W2)[tid];
    if (tid < 4)  wwp[tid] = ((const ull*)Ww)[tid];
    if (tid < 8)  b2s[tid] = b2[tid];
    const float bwv = __ldg(bw);

    const int start = chunk * CELLS_PER_CHUNK;
    const int end   = min(start + CELLS_PER_CHUNK, N_CELLS);

    const float4* __restrict__ Xg = (const float4*)(X + (size_t)b * N_CELLS * NI);

    float sw = 0.f;
    ull swh[4];
    #pragma unroll
    for (int k = 0; k < 4; ++k) swh[k] = pack2(0.f, 0.f);

    for (int base = start; base < end; base += CSTAGE) {
        __syncthreads();                 // covers weight init + buffer reuse
        const int nv = min(end - base, CSTAGE);

        // ---- coalesced stage: 128 cells x 64 floats -> swizzled SMEM ----
        #pragma unroll 8
        for (int k = 0; k < 16; ++k) {
            int f = tid + k * TPB;        // 0..2047
            int c = f >> 4;               // cell 0..127
            int o = f & 15;               // float4 slot
            float4 v = make_float4(0.f, 0.f, 0.f, 0.f);
            if (c < nv) v = Xg[(size_t)(base + c) * (NI / 4) + o];
            *(float4*)(xs + xs_off(c, o)) = v;
        }
        __syncthreads();

        const bool valid = (tid < nv);

        // ---- layer 1: 64 -> 16; W1 split between constant port and SMEM ----
        ull acc[8];
        #pragma unroll
        for (int jp = 0; jp < 8; ++jp)
            acc[jp] = pack2(cb1[2 * jp], cb1[2 * jp + 1]);

        #pragma unroll 4
        for (int i4 = 0; i4 < 16; ++i4) {
            float4 xv = *(const float4*)(xs + xs_off(tid, i4));
            #pragma unroll
            for (int s = 0; s < 4; ++s) {
                int i = i4 * 4 + s;
                float xc = (s == 0) ? xv.x : (s == 1) ? xv.y : (s == 2) ? xv.z : xv.w;
                ull x2 = pack2(xc, xc);
                if (i4 < 8) {
                    // rows 0..31: constant port
                    const ulonglong2* wr = (const ulonglong2*)&cW1p[i * 8];
                    #pragma unroll
                    for (int q = 0; q < 4; ++q) {
                        ulonglong2 w = wr[q];
                        acc[2 * q + 0] = fma2(x2, w.x, acc[2 * q + 0]);
                        acc[2 * q + 1] = fma2(x2, w.y, acc[2 * q + 1]);
                    }
                } else {
                    // rows 32..63: SMEM broadcast
                    const ulonglong2* wr = (const ulonglong2*)&w1s[(i - 32) * 8];
                    #pragma unroll
                    for (int q = 0; q < 4; ++q) {
                        ulonglong2 w = wr[q];
                        acc[2 * q + 0] = fma2(x2, w.x, acc[2 * q + 0]);
                        acc[2 * q + 1] = fma2(x2, w.y, acc[2 * q + 1]);
                    }
                }
            }
        }

        // ---- per-cell tail: relu -> layer2 -> relu -> gate -> accumulate ----
        float h1[H1];
        #pragma unroll
        for (int jp = 0; jp < 8; ++jp) {
            float lo, hi; unpack2(acc[jp], lo, hi);
            h1[2 * jp]     = fmaxf(lo, 0.f);
            h1[2 * jp + 1] = fmaxf(hi, 0.f);
        }

        ull acc2[4];
        #pragma unroll
        for (int kp = 0; kp < 4; ++kp) acc2[kp] = pack2(b2s[2 * kp], b2s[2 * kp + 1]);
        const ulonglong2* w2p = (const ulonglong2*)w2q;
        #pragma unroll
        for (int i = 0; i < H1; ++i) {
            ull hx = pack2(h1[i], h1[i]);
            ulonglong2 wa = w2p[i * 2 + 0];
            ulonglong2 wb = w2p[i * 2 + 1];
            acc2[0] = fma2(hx, wa.x, acc2[0]);
            acc2[1] = fma2(hx, wa.y, acc2[1]);
            acc2[2] = fma2(hx, wb.x, acc2[2]);
            acc2[3] = fma2(hx, wb.y, acc2[3]);
        }

        float h2[H2];
        #pragma unroll
        for (int kp = 0; kp < 4; ++kp) {
            float lo, hi; unpack2(acc2[kp], lo, hi);
            h2[2 * kp]     = fmaxf(lo, 0.f);
            h2[2 * kp + 1] = fmaxf(hi, 0.f);
        }

        ull g = pack2(bwv, 0.f);
        #pragma unroll
        for (int kp = 0; kp < 4; ++kp)
            g = fma2(pack2(h2[2 * kp], h2[2 * kp + 1]), wwp[kp], g);
        float glo, ghi; unpack2(g, glo, ghi);
        float wgt = 1.f / (1.f + __expf(-(glo + ghi)));
        if (!valid) wgt = 0.f;

        sw += wgt;
        ull wp = pack2(wgt, wgt);
        #pragma unroll
        for (int kp = 0; kp < 4; ++kp)
            swh[kp] = fma2(wp, pack2(h2[2 * kp], h2[2 * kp + 1]), swh[kp]);
    }

    // ---- deterministic block reduction of 9 values (4 warps) ----
    float vals[9];
    vals[0] = sw;
    #pragma unroll
    for (int kp = 0; kp < 4; ++kp) {
        float lo, hi; unpack2(swh[kp], lo, hi);
        vals[1 + 2 * kp] = lo; vals[2 + 2 * kp] = hi;
    }
    #pragma unroll
    for (int off = 16; off > 0; off >>= 1) {
        #pragma unroll
        for (int k = 0; k < 9; ++k)
            vals[k] += __shfl_down_sync(0xffffffffu, vals[k], off);
    }
    const int lane = tid & 31, warp = tid >> 5;
    if (lane == 0) {
        #pragma unroll
        for (int k = 0; k < 9; ++k) red[k * 4 + warp] = vals[k];
    }
    __syncthreads();
    if (tid < 9) {
        float s = 0.f;
        #pragma unroll
        for (int w = 0; w < 4; ++w) s += red[tid * 4 + w];
        g_partials[((size_t)b * CHUNKS + chunk) * 9 + tid] = s;
    }

    // ---- last-block finalize (fused head; graph-replay-safe counter) ----
    __threadfence();
    __syncthreads();
    if (tid == 0) {
        unsigned int d = atomicAdd(&g_count, 1u);
        s_last = (d == TOTAL_BLOCKS - 1) ? 1u : 0u;
    }
    __syncthreads();

    if (s_last) {
        float* fs = (float*)xs;          // reuse staging buffer: [64][9]
        for (int p = tid; p < B_SLIDES * 9; p += TPB) {
            int bb = p / 9, k = p % 9;
            float s = 0.f;
            #pragma unroll
            for (int c = 0; c < CHUNKS; ++c)
                s += ldcg(&g_partials[((size_t)bb * CHUNKS + c) * 9 + k]);
            fs[bb * 9 + k] = s;
        }
        __syncthreads();
        if (tid < B_SLIDES) {
            float inv = 1.f / fs[tid * 9];
            #pragma unroll
            for (int o = 0; o < N_OUT; ++o) {
                float r = b4[o];
                #pragma unroll
                for (int k = 0; k < H2; ++k)
                    r += (fs[tid * 9 + 1 + k] * inv) * W4[k * N_OUT + o];
                out[tid * N_OUT + o] = r;
            }
        }
        if (tid == 0) atomicExch(&g_count, 0u);   // reset for next graph replay
    }
}

extern "C" void kernel_launch(void* const* d_in, const int* in_sizes, int n_in,
                              void* d_out, int out_size)
{
    (void)in_sizes; (void)n_in; (void)out_size;

    // W1 low half + b1 into constant memory (raw D2D copies, graph-capturable).
    cudaMemcpyToSymbolAsync(cW1p, d_in[1], 32 * H1 * sizeof(float), 0,
                            cudaMemcpyDeviceToDevice, 0);
    cudaMemcpyToSymbolAsync(cb1,  d_in[2], H1 * sizeof(float), 0,
                            cudaMemcpyDeviceToDevice, 0);

    cudaFuncSetAttribute(mlp_pool_kernel,
                         cudaFuncAttributeMaxDynamicSharedMemorySize, SMEM_BYTES);
    dim3 grid(CHUNKS, B_SLIDES);
    mlp_pool_kernel<<<grid, TPB, SMEM_BYTES>>>(
        (const float*)d_in[0],
        (const float*)d_in[1], (const float*)d_in[2],
        (const float*)d_in[3], (const float*)d_in[4],
        (const float*)d_in[5], (const float*)d_in[6],
        (const float*)d_in[7], (const float*)d_in[8],
        (float*)d_out);
}

// round 10
// speedup vs baseline: 1.5131x; 1.0355x over previous
#include <cuda_runtime.h>
#include <cstdint>
#include <math.h>

#define B_SLIDES 64
#define N_CELLS  20000
#define NI       64
#define H1       16
#define H2       8
#define N_OUT    2

#define TPB      96                  // 3 warps
#define CSTAGE   96                  // cells per buffer (1 per thread)
#define CHUNKS   9
#define CELLS_PER_CHUNK ((N_CELLS + CHUNKS - 1) / CHUNKS)   // 2223
#define TOTAL_BLOCKS (CHUNKS * B_SLIDES)                    // 576 (<= 4*148=592, one wave)

// One staging buffer: 96 rows x 256 bytes, XOR-swizzled in 16B units
#define XS_BYTES (CSTAGE * 256)      // 24576
// two buffers + W1 high half (2KB) + W2 (512B) + small tails
#define SMEM_BYTES (2 * XS_BYTES + 2048 + 512 + 32 + 32 + 128 + 64)

typedef unsigned long long ull;

// ---- W1 low half (+b1) in constant memory (constant port) ----
__constant__ ull   cW1p[32 * H1 / 2];   // W1 rows 0..31 as fp32-pairs (2KB)
__constant__ float cb1[H1];

__device__ float        g_partials[B_SLIDES * CHUNKS * 9];
__device__ unsigned int g_count = 0;

__device__ __forceinline__ ull pack2(float lo, float hi) {
    ull r; asm("mov.b64 %0, {%1, %2};" : "=l"(r) : "f"(lo), "f"(hi)); return r;
}
__device__ __forceinline__ void unpack2(ull v, float& lo, float& hi) {
    asm("mov.b64 {%0, %1}, %2;" : "=f"(lo), "=f"(hi) : "l"(v));
}
// Packed fp32x2 FMA (sm_100+): two fp32 FMAs per instruction.
__device__ __forceinline__ ull fma2(ull a, ull b, ull c) {
    ull d; asm("fma.rn.f32x2 %0, %1, %2, %3;" : "=l"(d) : "l"(a), "l"(b), "l"(c)); return d;
}
__device__ __forceinline__ float ldcg(const float* p) {
    float v; asm("ld.global.cg.f32 %0, [%1];" : "=f"(v) : "l"(p)); return v;
}

// row-XOR swizzle: 16B column col within 256B row r -> col ^ (r & 7)
__device__ __forceinline__ uint32_t xs_off(int row, int col16) {
    return ((uint32_t)row << 8) + (((uint32_t)(col16 ^ (row & 7))) << 4);
}

// Async-copy one 96x64f tile (clamped at chunk end) into a swizzled buffer.
__device__ __forceinline__ void prefetch_tile(uint32_t smem_buf,
                                              const float4* __restrict__ Xg,
                                              int base, int chunk_end, int tid) {
    #pragma unroll
    for (int k = 0; k < 16; ++k) {
        int f = tid + k * TPB;        // 0..1535
        int c = f >> 4;               // cell 0..95
        int o = f & 15;               // float4 slot
        int n = base + c;
        if (n > chunk_end - 1) n = chunk_end - 1;   // clamp (data gated later)
        uint32_t dst = smem_buf + xs_off(c, o);
        const float4* src = &Xg[(size_t)n * (NI / 4) + o];
        asm volatile("cp.async.cg.shared.global [%0], [%1], 16;"
                     :: "r"(dst), "l"(src));
    }
    asm volatile("cp.async.commit_group;");
}

__global__ __launch_bounds__(TPB, 4) void mlp_pool_kernel(
    const float* __restrict__ X,
    const float* __restrict__ W1, const float* __restrict__ b1_unused,
    const float* __restrict__ W2, const float* __restrict__ b2,
    const float* __restrict__ Ww, const float* __restrict__ bw,
    const float* __restrict__ W4, const float* __restrict__ b4,
    float* __restrict__ out)
{
    extern __shared__ char smem[];
    char* xs0  = smem;                                    // buffer 0 (24KB)
    ull*  w1s  = (ull*)(smem + 2 * XS_BYTES);             // 256 ull: W1 rows 32..63
    ull*  w2q  = w1s + 256;                               // 64 ull (W2 raw pairs)
    ull*  wwp  = w2q + 64;                                // 4 ull
    float* b2s = (float*)(wwp + 4);                       // 8
    float* red = b2s + 8;                                 // 9 * 3
    __shared__ unsigned int s_last;

    const int tid   = threadIdx.x;
    const int b     = blockIdx.y;
    const int chunk = blockIdx.x;

    const uint32_t xs_base = (uint32_t)__cvta_generic_to_shared(smem);

    // ---- weights -> SMEM: W1 high half + small tail weights ----
    {
        const ull* W1q = (const ull*)W1;                  // [64][8] pairs
        #pragma unroll
        for (int k = tid; k < 256; k += TPB)
            w1s[k] = W1q[256 + k];                        // rows 32..63
    }
    if (tid < 64) w2q[tid] = ((const ull*)W2)[tid];
    if (tid < 4)  wwp[tid] = ((const ull*)Ww)[tid];
    if (tid < 8)  b2s[tid] = b2[tid];
    const float bwv = __ldg(bw);

    const int start = chunk * CELLS_PER_CHUNK;
    const int end   = min(start + CELLS_PER_CHUNK, N_CELLS);

    const float4* __restrict__ Xg = (const float4*)(X + (size_t)b * N_CELLS * NI);

    float sw = 0.f;
    ull swh[4];
    #pragma unroll
    for (int k = 0; k < 4; ++k) swh[k] = pack2(0.f, 0.f);

    // ---- double-buffered cp.async pipeline ----
    prefetch_tile(xs_base, Xg, start, end, tid);
    int nbuf = 0;

    for (int base = start; base < end; base += CSTAGE) {
        const bool more = (base + CSTAGE) < end;
        if (more)
            prefetch_tile(xs_base + (nbuf ^ 1) * XS_BYTES, Xg, base + CSTAGE, end, tid);

        if (more) asm volatile("cp.async.wait_group 1;");
        else      asm volatile("cp.async.wait_group 0;");
        __syncthreads();                                  // buffer visible to all

        const char* xb = smem + nbuf * XS_BYTES;
        const int nv = min(end - base, CSTAGE);
        const bool valid = (tid < nv);

        // ---- layer 1: 64 -> 16; W1 split between constant port and SMEM ----
        ull acc[8];
        #pragma unroll
        for (int jp = 0; jp < 8; ++jp)
            acc[jp] = pack2(cb1[2 * jp], cb1[2 * jp + 1]);

        #pragma unroll 4
        for (int i4 = 0; i4 < 16; ++i4) {
            float4 xv = *(const float4*)(xb + xs_off(tid, i4));
            #pragma unroll
            for (int s = 0; s < 4; ++s) {
                int i = i4 * 4 + s;
                float xc = (s == 0) ? xv.x : (s == 1) ? xv.y : (s == 2) ? xv.z : xv.w;
                ull x2 = pack2(xc, xc);
                if (i4 < 8) {
                    const ulonglong2* wr = (const ulonglong2*)&cW1p[i * 8];
                    #pragma unroll
                    for (int q = 0; q < 4; ++q) {
                        ulonglong2 w = wr[q];
                        acc[2 * q + 0] = fma2(x2, w.x, acc[2 * q + 0]);
                        acc[2 * q + 1] = fma2(x2, w.y, acc[2 * q + 1]);
                    }
                } else {
                    const ulonglong2* wr = (const ulonglong2*)&w1s[(i - 32) * 8];
                    #pragma unroll
                    for (int q = 0; q < 4; ++q) {
                        ulonglong2 w = wr[q];
                        acc[2 * q + 0] = fma2(x2, w.x, acc[2 * q + 0]);
                        acc[2 * q + 1] = fma2(x2, w.y, acc[2 * q + 1]);
                    }
                }
            }
        }

        // ---- per-cell tail ----
        float h1[H1];
        #pragma unroll
        for (int jp = 0; jp < 8; ++jp) {
            float lo, hi; unpack2(acc[jp], lo, hi);
            h1[2 * jp]     = fmaxf(lo, 0.f);
            h1[2 * jp + 1] = fmaxf(hi, 0.f);
        }

        ull acc2[4];
        #pragma unroll
        for (int kp = 0; kp < 4; ++kp) acc2[kp] = pack2(b2s[2 * kp], b2s[2 * kp + 1]);
        const ulonglong2* w2p = (const ulonglong2*)w2q;
        #pragma unroll
        for (int i = 0; i < H1; ++i) {
            ull hx = pack2(h1[i], h1[i]);
            ulonglong2 wa = w2p[i * 2 + 0];
            ulonglong2 wb = w2p[i * 2 + 1];
            acc2[0] = fma2(hx, wa.x, acc2[0]);
            acc2[1] = fma2(hx, wa.y, acc2[1]);
            acc2[2] = fma2(hx, wb.x, acc2[2]);
            acc2[3] = fma2(hx, wb.y, acc2[3]);
        }

        float h2[H2];
        #pragma unroll
        for (int kp = 0; kp < 4; ++kp) {
            float lo, hi; unpack2(acc2[kp], lo, hi);
            h2[2 * kp]     = fmaxf(lo, 0.f);
            h2[2 * kp + 1] = fmaxf(hi, 0.f);
        }

        ull g = pack2(bwv, 0.f);
        #pragma unroll
        for (int kp = 0; kp < 4; ++kp)
            g = fma2(pack2(h2[2 * kp], h2[2 * kp + 1]), wwp[kp], g);
        float glo, ghi; unpack2(g, glo, ghi);
        float wgt = 1.f / (1.f + __expf(-(glo + ghi)));
        if (!valid) wgt = 0.f;

        sw += wgt;
        ull wp = pack2(wgt, wgt);
        #pragma unroll
        for (int kp = 0; kp < 4; ++kp)
            swh[kp] = fma2(wp, pack2(h2[2 * kp], h2[2 * kp + 1]), swh[kp]);

        __syncthreads();        // all consumed before next prefetch overwrites
        nbuf ^= 1;
    }

    // ---- deterministic block reduction of 9 values (3 warps) ----
    float vals[9];
    vals[0] = sw;
    #pragma unroll
    for (int kp = 0; kp < 4; ++kp) {
        float lo, hi; unpack2(swh[kp], lo, hi);
        vals[1 + 2 * kp] = lo; vals[2 + 2 * kp] = hi;
    }
    #pragma unroll
    for (int off = 16; off > 0; off >>= 1) {
        #pragma unroll
        for (int k = 0; k < 9; ++k)
            vals[k] += __shfl_down_sync(0xffffffffu, vals[k], off);
    }
    const int lane = tid & 31, warp = tid >> 5;
    if (lane == 0) {
        #pragma unroll
        for (int k = 0; k < 9; ++k) red[k * 3 + warp] = vals[k];
    }
    __syncthreads();
    if (tid < 9)
        g_partials[((size_t)b * CHUNKS + chunk) * 9 + tid] =
            red[tid * 3] + red[tid * 3 + 1] + red[tid * 3 + 2];

    // ---- last-block finalize (fused head; graph-replay-safe counter) ----
    __threadfence();
    __syncthreads();
    if (tid == 0) {
        unsigned int d = atomicAdd(&g_count, 1u);
        s_last = (d == TOTAL_BLOCKS - 1) ? 1u : 0u;
    }
    __syncthreads();

    if (s_last) {
        float* fs = (float*)smem;        // reuse staging buffer: [64][9]
        for (int p = tid; p < B_SLIDES * 9; p += TPB) {
            int bb = p / 9, k = p % 9;
            float s = 0.f;
            #pragma unroll
            for (int c = 0; c < CHUNKS; ++c)
                s += ldcg(&g_partials[((size_t)bb * CHUNKS + c) * 9 + k]);
            fs[bb * 9 + k] = s;
        }
        __syncthreads();
        if (tid < B_SLIDES) {
            float inv = 1.f / fs[tid * 9];
            #pragma unroll
            for (int o = 0; o < N_OUT; ++o) {
                float r = b4[o];
                #pragma unroll
                for (int k = 0; k < H2; ++k)
                    r += (fs[tid * 9 + 1 + k] * inv) * W4[k * N_OUT + o];
                out[tid * N_OUT + o] = r;
            }
        }
        if (tid == 0) atomicExch(&g_count, 0u);   // reset for next graph replay
    }
}

extern "C" void kernel_launch(void* const* d_in, const int* in_sizes, int n_in,
                              void* d_out, int out_size)
{
    (void)in_sizes; (void)n_in; (void)out_size;

    // W1 low half + b1 into constant memory (raw D2D copies, graph-capturable).
    cudaMemcpyToSymbolAsync(cW1p, d_in[1], 32 * H1 * sizeof(float), 0,
                            cudaMemcpyDeviceToDevice, 0);
    cudaMemcpyToSymbolAsync(cb1,  d_in[2], H1 * sizeof(float), 0,
                            cudaMemcpyDeviceToDevice, 0);

    cudaFuncSetAttribute(mlp_pool_kernel,
                         cudaFuncAttributeMaxDynamicSharedMemorySize, SMEM_BYTES);
    dim3 grid(CHUNKS, B_SLIDES);
    mlp_pool_kernel<<<grid, TPB, SMEM_BYTES>>>(
        (const float*)d_in[0],
        (const float*)d_in[1], (const float*)d_in[2],
        (const float*)d_in[3], (const float*)d_in[4],
        (const float*)d_in[5], (const float*)d_in[6],
        (const float*)d_in[7], (const float*)d_in[8],
        (float*)d_out);
}

// round 11
// speedup vs baseline: 1.5265x; 1.0088x over previous
#include <cuda_runtime.h>
#include <cstdint>
#include <math.h>

#define B_SLIDES 64
#define N_CELLS  20000
#define NI       64
#define H1       16
#define H2       8
#define N_OUT    2

#define TPB      128                 // 4 warps
#define CSTAGE   128                 // cells per buffer (1 per thread)
#define CHUNKS   13
#define CELLS_PER_CHUNK ((N_CELLS + CHUNKS - 1) / CHUNKS)   // 1539
#define TOTAL_BLOCKS (CHUNKS * B_SLIDES)                    // 832 (<= 6*148=888, one wave)

// Staging buffer: 128 rows x 256 bytes, XOR-swizzled in 16B units
#define XS_BYTES (CSTAGE * 256)      // 32768
#define SMEM_BYTES (XS_BYTES + 512 + 32 + 32 + 160 + 64)

typedef unsigned long long ull;

// ---- FULL W1 (+b1) in constant memory: weight loads on the constant port ----
__constant__ ull   cW1p[NI * H1 / 2];   // W1[64][16] raw -> [64][8] fp32-pairs (4KB)
__constant__ float cb1[H1];

__device__ float        g_partials[B_SLIDES * CHUNKS * 9];
__device__ unsigned int g_count = 0;

__device__ __forceinline__ ull pack2(float lo, float hi) {
    ull r; asm("mov.b64 %0, {%1, %2};" : "=l"(r) : "f"(lo), "f"(hi)); return r;
}
__device__ __forceinline__ void unpack2(ull v, float& lo, float& hi) {
    asm("mov.b64 {%0, %1}, %2;" : "=f"(lo), "=f"(hi) : "l"(v));
}
// Packed fp32x2 FMA (sm_100+): two fp32 FMAs per instruction.
__device__ __forceinline__ ull fma2(ull a, ull b, ull c) {
    ull d; asm("fma.rn.f32x2 %0, %1, %2, %3;" : "=l"(d) : "l"(a), "l"(b), "l"(c)); return d;
}
__device__ __forceinline__ float ldcg(const float* p) {
    float v; asm("ld.global.cg.f32 %0, [%1];" : "=f"(v) : "l"(p)); return v;
}

// row-XOR swizzle: 16B column col within 256B row r -> col ^ (r & 7)
__device__ __forceinline__ uint32_t xs_off(int row, int col16) {
    return ((uint32_t)row << 8) + (((uint32_t)(col16 ^ (row & 7))) << 4);
}

__global__ __launch_bounds__(TPB, 6) void mlp_pool_kernel(
    const float* __restrict__ X,
    const float* __restrict__ W2, const float* __restrict__ b2,
    const float* __restrict__ Ww, const float* __restrict__ bw,
    const float* __restrict__ W4, const float* __restrict__ b4,
    float* __restrict__ out)
{
    extern __shared__ char smem[];
    char*  xs  = smem;                                    // 32KB swizzled staging
    ull*   w2q = (ull*)(smem + XS_BYTES);                 // 64 ull (W2 raw pairs)
    ull*   wwp = w2q + 64;                                // 4 ull
    float* b2s = (float*)(wwp + 4);                       // 8
    float* red = b2s + 8;                                 // 9 * 4
    __shared__ unsigned int s_last;

    const int tid   = threadIdx.x;
    const int b     = blockIdx.y;
    const int chunk = blockIdx.x;

    const uint32_t xs_base = (uint32_t)__cvta_generic_to_shared(smem);

    // ---- small tail weights -> SMEM ----
    if (tid < 64) w2q[tid] = ((const ull*)W2)[tid];
    if (tid < 4)  wwp[tid] = ((const ull*)Ww)[tid];
    if (tid < 8)  b2s[tid] = b2[tid];
    const float bwv = __ldg(bw);

    const int start = chunk * CELLS_PER_CHUNK;
    const int end   = min(start + CELLS_PER_CHUNK, N_CELLS);

    const float4* __restrict__ Xg = (const float4*)(X + (size_t)b * N_CELLS * NI);

    float sw = 0.f;
    ull swh[4];
    #pragma unroll
    for (int k = 0; k < 4; ++k) swh[k] = pack2(0.f, 0.f);

    for (int base = start; base < end; base += CSTAGE) {
        __syncthreads();                     // buffer consumed by all (and smem init)

        // ---- cp.async stage: 128 cells x 64 floats -> swizzled SMEM ----
        // GMEM -> SMEM directly: no register landing, .cg bypasses L1 data path.
        #pragma unroll
        for (int k = 0; k < 16; ++k) {
            int f = tid + k * TPB;            // 0..2047
            int c = f >> 4;                   // cell 0..127
            int o = f & 15;                   // float4 slot
            int n = base + c;
            if (n > end - 1) n = end - 1;     // clamp (gated by valid below)
            uint32_t dst = xs_base + xs_off(c, o);
            const float4* src = &Xg[(size_t)n * (NI / 4) + o];
            asm volatile("cp.async.cg.shared.global [%0], [%1], 16;"
                         :: "r"(dst), "l"(src));
        }
        asm volatile("cp.async.commit_group;");
        asm volatile("cp.async.wait_group 0;");
        __syncthreads();

        const int nv = min(end - base, CSTAGE);
        const bool valid = (tid < nv);

        // ---- layer 1: 64 -> 16; all W1 from the constant port ----
        ull acc[8];
        #pragma unroll
        for (int jp = 0; jp < 8; ++jp)
            acc[jp] = pack2(cb1[2 * jp], cb1[2 * jp + 1]);

        #pragma unroll 4
        for (int i4 = 0; i4 < 16; ++i4) {
            float4 xv = *(const float4*)(xs + xs_off(tid, i4));
            #pragma unroll
            for (int s = 0; s < 4; ++s) {
                int i = i4 * 4 + s;
                float xc = (s == 0) ? xv.x : (s == 1) ? xv.y : (s == 2) ? xv.z : xv.w;
                ull x2 = pack2(xc, xc);
                const ulonglong2* wr = (const ulonglong2*)&cW1p[i * 8];
                #pragma unroll
                for (int q = 0; q < 4; ++q) {
                    ulonglong2 w = wr[q];     // constant port, warp-uniform
                    acc[2 * q + 0] = fma2(x2, w.x, acc[2 * q + 0]);
                    acc[2 * q + 1] = fma2(x2, w.y, acc[2 * q + 1]);
                }
            }
        }

        // ---- per-cell tail: relu -> layer2 -> relu -> gate -> accumulate ----
        float h1[H1];
        #pragma unroll
        for (int jp = 0; jp < 8; ++jp) {
            float lo, hi; unpack2(acc[jp], lo, hi);
            h1[2 * jp]     = fmaxf(lo, 0.f);
            h1[2 * jp + 1] = fmaxf(hi, 0.f);
        }

        ull acc2[4];
        #pragma unroll
        for (int kp = 0; kp < 4; ++kp) acc2[kp] = pack2(b2s[2 * kp], b2s[2 * kp + 1]);
        const ulonglong2* w2p = (const ulonglong2*)w2q;
        #pragma unroll
        for (int i = 0; i < H1; ++i) {
            ull hx = pack2(h1[i], h1[i]);
            ulonglong2 wa = w2p[i * 2 + 0];
            ulonglong2 wb = w2p[i * 2 + 1];
            acc2[0] = fma2(hx, wa.x, acc2[0]);
            acc2[1] = fma2(hx, wa.y, acc2[1]);
            acc2[2] = fma2(hx, wb.x, acc2[2]);
            acc2[3] = fma2(hx, wb.y, acc2[3]);
        }

        float h2[H2];
        #pragma unroll
        for (int kp = 0; kp < 4; ++kp) {
            float lo, hi; unpack2(acc2[kp], lo, hi);
            h2[2 * kp]     = fmaxf(lo, 0.f);
            h2[2 * kp + 1] = fmaxf(hi, 0.f);
        }

        ull g = pack2(bwv, 0.f);
        #pragma unroll
        for (int kp = 0; kp < 4; ++kp)
            g = fma2(pack2(h2[2 * kp], h2[2 * kp + 1]), wwp[kp], g);
        float glo, ghi; unpack2(g, glo, ghi);
        float wgt = 1.f / (1.f + __expf(-(glo + ghi)));
        if (!valid) wgt = 0.f;

        sw += wgt;
        ull wp = pack2(wgt, wgt);
        #pragma unroll
        for (int kp = 0; kp < 4; ++kp)
            swh[kp] = fma2(wp, pack2(h2[2 * kp], h2[2 * kp + 1]), swh[kp]);
    }

    // ---- deterministic block reduction of 9 values (4 warps) ----
    float vals[9];
    vals[0] = sw;
    #pragma unroll
    for (int kp = 0; kp < 4; ++kp) {
        float lo, hi; unpack2(swh[kp], lo, hi);
        vals[1 + 2 * kp] = lo; vals[2 + 2 * kp] = hi;
    }
    #pragma unroll
    for (int off = 16; off > 0; off >>= 1) {
        #pragma unroll
        for (int k = 0; k < 9; ++k)
            vals[k] += __shfl_down_sync(0xffffffffu, vals[k], off);
    }
    const int lane = tid & 31, warp = tid >> 5;
    if (lane == 0) {
        #pragma unroll
        for (int k = 0; k < 9; ++k) red[k * 4 + warp] = vals[k];
    }
    __syncthreads();
    if (tid < 9) {
        float s = 0.f;
        #pragma unroll
        for (int w = 0; w < 4; ++w) s += red[tid * 4 + w];
        g_partials[((size_t)b * CHUNKS + chunk) * 9 + tid] = s;
    }

    // ---- last-block finalize (fused head; graph-replay-safe counter) ----
    __threadfence();
    __syncthreads();
    if (tid == 0) {
        unsigned int d = atomicAdd(&g_count, 1u);
        s_last = (d == TOTAL_BLOCKS - 1) ? 1u : 0u;
    }
    __syncthreads();

    if (s_last) {
        float* fs = (float*)xs;          // reuse staging buffer: [64][9]
        for (int p = tid; p < B_SLIDES * 9; p += TPB) {
            int bb = p / 9, k = p % 9;
            float s = 0.f;
            #pragma unroll
            for (int c = 0; c < CHUNKS; ++c)
                s += ldcg(&g_partials[((size_t)bb * CHUNKS + c) * 9 + k]);
            fs[bb * 9 + k] = s;
        }
        __syncthreads();
        if (tid < B_SLIDES) {
            float inv = 1.f / fs[tid * 9];
            #pragma unroll
            for (int o = 0; o < N_OUT; ++o) {
                float r = b4[o];
                #pragma unroll
                for (int k = 0; k < H2; ++k)
                    r += (fs[tid * 9 + 1 + k] * inv) * W4[k * N_OUT + o];
                out[tid * N_OUT + o] = r;
            }
        }
        if (tid == 0) atomicExch(&g_count, 0u);   // reset for next graph replay
    }
}

extern "C" void kernel_launch(void* const* d_in, const int* in_sizes, int n_in,
                              void* d_out, int out_size)
{
    (void)in_sizes; (void)n_in; (void)out_size;

    // Full W1 + b1 into constant memory (raw D2D copies, graph-capturable).
    cudaMemcpyToSymbolAsync(cW1p, d_in[1], NI * H1 * sizeof(float), 0,
                            cudaMemcpyDeviceToDevice, 0);
    cudaMemcpyToSymbolAsync(cb1,  d_in[2], H1 * sizeof(float), 0,
                            cudaMemcpyDeviceToDevice, 0);

    cudaFuncSetAttribute(mlp_pool_kernel,
                         cudaFuncAttributeMaxDynamicSharedMemorySize, SMEM_BYTES);
    dim3 grid(CHUNKS, B_SLIDES);
    mlp_pool_kernel<<<grid, TPB, SMEM_BYTES>>>(
        (const float*)d_in[0],
        (const float*)d_in[3], (const float*)d_in[4],
        (const float*)d_in[5], (const float*)d_in[6],
        (const float*)d_in[7], (const float*)d_in[8],
        (float*)d_out);
}